// round 9
// baseline (speedup 1.0000x reference)
#include <cuda_runtime.h>
#include <cstdio>

// MuHopf oscillator bank: B=128, D=1024, 256 steps.
// Output (float32, 33,816,576 elems): zs.real [256,128,1024] (astype(f32)
// drops imag), then r_f [128,1024], then phi_f [128,1024].

#define BB 128
#define DD 1024
#define BD (BB * DD)
#define STEPS 256
#define ANCHOR 16
#define DT 0.01f

__global__ void __launch_bounds__(256) muhopf_kernel(
    const float* __restrict__ x,
    const float* __restrict__ r0,
    const float* __restrict__ phi0,
    const float* __restrict__ w,
    float* __restrict__ out)
{
    int idx = blockIdx.x * blockDim.x + threadIdx.x;
    if (idx >= BD) return;
    int d = idx & (DD - 1);

    // omega = (sigmoid(w)*(5-0.5)+0.5) * 2*pi ; dphi = omega*dt
    float wraw  = w[d];
    float sig   = 1.0f / (1.0f + expf(-wraw));
    float omega = fmaf(sig, 4.5f, 0.5f) * 6.2831855f;
    float dphi  = omega * DT;

    float mu  = 5.0f * (1.0f + x[idx]);
    float r   = r0[idx];
    float phi = phi0[idx];      // sequentially accumulated, matching reference

    float cd, sd;
    sincosf(dphi, &sd, &cd);

    float* zs_re = out + idx;

    #pragma unroll 1
    for (int s0 = 0; s0 < STEPS; s0 += ANCHOR) {
        // re-anchor rotation state from the sequentially-accumulated phase
        float c, s;
        sincosf(phi + dphi, &s, &c);   // cos/sin of phi after the NEXT step

        #pragma unroll
        for (int i = 0; i < ANCHOR; i++) {
            // r_{n+1} = r + (mu - r^2) * r * dt
            float t = fmaf(-r, r, mu);
            r = fmaf(t * r, DT, r);
            // phi_{n+1} = phi_n + dphi (sequential fp32, matches reference)
            phi = phi + dphi;
            // Re(z_{n+1}) = r_{n+1} * cos(phi_{n+1})
            __stcs(&zs_re[(size_t)(s0 + i) * BD], r * c);
            // rotate (c,s) by dphi for the next step
            float cn = fmaf(c, cd, -s * sd);
            float sn = fmaf(s, cd,  c * sd);
            c = cn; s = sn;
        }
    }

    // tails: r_f then phi_f, raw float32 after zs.real
    out[(size_t)STEPS * BD + idx]      = r;
    out[(size_t)STEPS * BD + BD + idx] = phi;
}

extern "C" void kernel_launch(void* const* d_in, const int* in_sizes, int n_in,
                              void* d_out, int out_size)
{
    // ABI confirmed R7: d_in = {x[131072], r[131072], phi[131072], omegas_raw[1024]},
    // out_size = 33,816,576 float32 elements.
    const float* x   = (const float*)d_in[0];
    const float* r   = (const float*)d_in[1];
    const float* phi = (const float*)d_in[2];
    const float* w   = (const float*)d_in[3];

    // keep size-based rebinding as a safety net (order-agnostic)
    {
        const float* big[3] = {0, 0, 0};
        const float* ww = 0;
        int nbig = 0;
        for (int i = 0; i < n_in; i++) {
            if (in_sizes[i] == DD) { if (!ww) ww = (const float*)d_in[i]; }
            else if (in_sizes[i] == BD && nbig < 3) big[nbig++] = (const float*)d_in[i];
        }
        if (ww && nbig == 3) { x = big[0]; r = big[1]; phi = big[2]; w = ww; }
    }

    muhopf_kernel<<<BD / 256, 256>>>(x, r, phi, w, (float*)d_out);
}

// round 10
// speedup vs baseline: 1.0094x; 1.0094x over previous
#include <cuda_runtime.h>

// MuHopf oscillator bank: B=128, D=1024, 256 steps.
// Output (float32, 33,816,576 elems): zs.real [256,128,1024], r_f, phi_f.
// R9: 2 oscillators/thread, STG.64 stores (halves LSU dispatch pressure),
// 64-thread blocks for wave balance.

#define BB 128
#define DD 1024
#define BD (BB * DD)
#define BD2 (BD / 2)
#define STEPS 256
#define ANCHOR 16
#define DT 0.01f

__global__ void __launch_bounds__(64) muhopf_kernel(
    const float2* __restrict__ x2,
    const float2* __restrict__ r2,
    const float2* __restrict__ phi2,
    const float2* __restrict__ w2,
    float2* __restrict__ out2)
{
    int t = blockIdx.x * 64 + threadIdx.x;     // 0 .. BD2-1
    if (t >= BD2) return;
    int d2 = t & (DD / 2 - 1);

    // omega = (sigmoid(w)*4.5 + 0.5) * 2*pi ; dphi = omega*dt
    float2 wv = w2[d2];
    float sa = 1.0f / (1.0f + expf(-wv.x));
    float sb = 1.0f / (1.0f + expf(-wv.y));
    float dpa = fmaf(sa, 4.5f, 0.5f) * 6.2831855f * DT;
    float dpb = fmaf(sb, 4.5f, 0.5f) * 6.2831855f * DT;

    float2 xv = x2[t];
    float2 rv = r2[t];
    float2 pv = phi2[t];
    float mua = 5.0f * (1.0f + xv.x);
    float mub = 5.0f * (1.0f + xv.y);
    float ra = rv.x,  rb = rv.y;
    float pa = pv.x,  pb = pv.y;     // sequential fp32 accumulation (matches ref)

    float cda, sda, cdb, sdb;
    sincosf(dpa, &sda, &cda);
    sincosf(dpb, &sdb, &cdb);

    float2* zs = out2 + t;

    #pragma unroll 1
    for (int s0 = 0; s0 < STEPS; s0 += ANCHOR) {
        // re-anchor rotation state from the sequentially-accumulated phase
        float ca, sna, cb, snb;
        sincosf(pa + dpa, &sna, &ca);   // cos/sin of phi after the NEXT step
        sincosf(pb + dpb, &snb, &cb);

        #pragma unroll
        for (int i = 0; i < ANCHOR; i++) {
            // r_{n+1} = r + (mu - r^2) * r * dt
            float ta = fmaf(-ra, ra, mua);
            float tb = fmaf(-rb, rb, mub);
            ra = fmaf(ta * ra, DT, ra);
            rb = fmaf(tb * rb, DT, rb);
            pa = pa + dpa;
            pb = pb + dpb;
            // Re(z_{n+1}) = r_{n+1} * cos(phi_{n+1}), two lanes packed
            __stcs(&zs[(size_t)(s0 + i) * BD2], make_float2(ra * ca, rb * cb));
            // rotate (c,s) by dphi for the next step
            float cna = fmaf(ca, cda, -sna * sda);
            float nsa = fmaf(sna, cda,  ca * sda);
            float cnb = fmaf(cb, cdb, -snb * sdb);
            float nsb = fmaf(snb, cdb,  cb * sdb);
            ca = cna; sna = nsa;
            cb = cnb; snb = nsb;
        }
    }

    // tails: r_f then phi_f (float2 views of contiguous float arrays)
    out2[(size_t)STEPS * BD2 + t]       = make_float2(ra, rb);
    out2[(size_t)STEPS * BD2 + BD2 + t] = make_float2(pa, pb);
}

extern "C" void kernel_launch(void* const* d_in, const int* in_sizes, int n_in,
                              void* d_out, int out_size)
{
    // ABI (confirmed R7): {x[131072], r[131072], phi[131072], omegas_raw[1024]},
    // out = 33,816,576 float32.
    const float* x   = (const float*)d_in[0];
    const float* r   = (const float*)d_in[1];
    const float* phi = (const float*)d_in[2];
    const float* w   = (const float*)d_in[3];

    // order-agnostic safety net
    {
        const float* big[3] = {0, 0, 0};
        const float* ww = 0;
        int nbig = 0;
        for (int i = 0; i < n_in; i++) {
            if (in_sizes[i] == DD) { if (!ww) ww = (const float*)d_in[i]; }
            else if (in_sizes[i] == BD && nbig < 3) big[nbig++] = (const float*)d_in[i];
        }
        if (ww && nbig == 3) { x = big[0]; r = big[1]; phi = big[2]; w = ww; }
    }

    muhopf_kernel<<<BD2 / 64, 64>>>((const float2*)x, (const float2*)r,
                                    (const float2*)phi, (const float2*)w,
                                    (float2*)d_out);
}

// round 11
// speedup vs baseline: 1.0264x; 1.0168x over previous
#include <cuda_runtime.h>

// MuHopf oscillator bank: B=128, D=1024, 256 steps.
// Output (float32, 33,816,576 elems): zs.real [256,128,1024], r_f, phi_f.
// R11: Chebyshev cosine recurrence (1 FMA/step for the phase factor),
// phi evaluated per-anchor; 2 osc/thread, STG.64, 64-thread blocks.

#define BB 128
#define DD 1024
#define BD (BB * DD)
#define BD2 (BD / 2)
#define STEPS 256
#define ANCHOR 16
#define DT 0.01f

__global__ void __launch_bounds__(64) muhopf_kernel(
    const float2* __restrict__ x2,
    const float2* __restrict__ r2,
    const float2* __restrict__ phi2,
    const float2* __restrict__ w2,
    float2* __restrict__ out2)
{
    int t = blockIdx.x * 64 + threadIdx.x;     // 0 .. BD2-1
    if (t >= BD2) return;
    int d2 = t & (DD / 2 - 1);

    // dphi = (sigmoid(w)*4.5 + 0.5) * 2*pi * dt
    float2 wv = w2[d2];
    float sa = 1.0f / (1.0f + expf(-wv.x));
    float sb = 1.0f / (1.0f + expf(-wv.y));
    float dpa = fmaf(sa, 4.5f, 0.5f) * 6.2831855f * DT;
    float dpb = fmaf(sb, 4.5f, 0.5f) * 6.2831855f * DT;

    float2 xv = x2[t];
    float2 rv = r2[t];
    float2 pv = phi2[t];
    float mua = 5.0f * (1.0f + xv.x);
    float mub = 5.0f * (1.0f + xv.y);
    float ra = rv.x,  rb = rv.y;
    float p0a = pv.x, p0b = pv.y;

    // one-step rotation constants and Chebyshev coefficient k = 2*cos(dphi)
    float cda, sda, cdb, sdb;
    sincosf(dpa, &sda, &cda);
    sincosf(dpb, &sdb, &cdb);
    float ka = 2.0f * cda;
    float kb = 2.0f * cdb;

    float2* zs = out2 + t;

    #pragma unroll 1
    for (int s0 = 0; s0 < STEPS; s0 += ANCHOR) {
        // anchor: phi after s0 steps, exact trig re-seed
        float pha = fmaf((float)s0, dpa, p0a);
        float phb = fmaf((float)s0, dpb, p0b);
        float c0a, s0a, c0b, s0b;
        sincosf(pha, &s0a, &c0a);
        sincosf(phb, &s0b, &c0b);
        // cm = cos(phi_s0), c = cos(phi_s0 + dphi)
        float cma = c0a, cmb = c0b;
        float ca = fmaf(c0a, cda, -s0a * sda);
        float cb = fmaf(c0b, cdb, -s0b * sdb);

        #pragma unroll
        for (int i = 0; i < ANCHOR; i++) {
            // r_{n+1} = r + (mu - r^2) * r * dt
            float ta = fmaf(-ra, ra, mua);
            float tb = fmaf(-rb, rb, mub);
            ra = fmaf(ta * ra, DT, ra);
            rb = fmaf(tb * rb, DT, rb);
            // Re(z_{n+1}) = r_{n+1} * cos(phi_{n+1})  (c currently = cos after step i)
            __stcs(&zs[(size_t)(s0 + i) * BD2], make_float2(ra * ca, rb * cb));
            // Chebyshev: cos(phi + (i+2)dphi) = k*cos(phi+(i+1)dphi) - cos(phi+i*dphi)
            float cna = fmaf(ka, ca, -cma);
            float cnb = fmaf(kb, cb, -cmb);
            cma = ca; ca = cna;
            cmb = cb; cb = cnb;
        }
    }

    // tails: r_f then phi_f
    out2[(size_t)STEPS * BD2 + t]       = make_float2(ra, rb);
    out2[(size_t)STEPS * BD2 + BD2 + t] =
        make_float2(fmaf((float)STEPS, dpa, p0a), fmaf((float)STEPS, dpb, p0b));
}

extern "C" void kernel_launch(void* const* d_in, const int* in_sizes, int n_in,
                              void* d_out, int out_size)
{
    // ABI (confirmed R7): {x[131072], r[131072], phi[131072], omegas_raw[1024]},
    // out = 33,816,576 float32.
    const float* x   = (const float*)d_in[0];
    const float* r   = (const float*)d_in[1];
    const float* phi = (const float*)d_in[2];
    const float* w   = (const float*)d_in[3];

    // order-agnostic safety net
    {
        const float* big[3] = {0, 0, 0};
        const float* ww = 0;
        int nbig = 0;
        for (int i = 0; i < n_in; i++) {
            if (in_sizes[i] == DD) { if (!ww) ww = (const float*)d_in[i]; }
            else if (in_sizes[i] == BD && nbig < 3) big[nbig++] = (const float*)d_in[i];
        }
        if (ww && nbig == 3) { x = big[0]; r = big[1]; phi = big[2]; w = ww; }
    }

    muhopf_kernel<<<BD2 / 64, 64>>>((const float2*)x, (const float2*)r,
                                    (const float2*)phi, (const float2*)w,
                                    (float2*)d_out);
}

// round 12
// speedup vs baseline: 1.0276x; 1.0012x over previous
#include <cuda_runtime.h>

// MuHopf oscillator bank: B=128, D=1024, 256 steps.
// Output (float32, 33,816,576 elems): zs.real [256,128,1024], r_f, phi_f.
// R12: 4 osc/thread + STG.128 (LSU issue cost 12 vs 15.5/20 cyc per 16B),
// Chebyshev cosine recurrence, 32-thread blocks (1% wave tail).

#define BB 128
#define DD 1024
#define BD (BB * DD)
#define BD4 (BD / 4)
#define STEPS 256
#define ANCHOR 16
#define DT 0.01f

__global__ void __launch_bounds__(32) muhopf_kernel(
    const float4* __restrict__ x4,
    const float4* __restrict__ r4,
    const float4* __restrict__ phi4,
    const float4* __restrict__ w4,
    float4* __restrict__ out4)
{
    int t = blockIdx.x * 32 + threadIdx.x;     // 0 .. BD4-1
    if (t >= BD4) return;
    int d4 = t & (DD / 4 - 1);

    // dphi = (sigmoid(w)*4.5 + 0.5) * 2*pi * dt, per lane
    float4 wv = w4[d4];
    float dp[4];
    {
        float wr[4] = {wv.x, wv.y, wv.z, wv.w};
        #pragma unroll
        for (int j = 0; j < 4; j++) {
            float s = 1.0f / (1.0f + expf(-wr[j]));
            dp[j] = fmaf(s, 4.5f, 0.5f) * 6.2831855f * DT;
        }
    }

    float4 xv = x4[t];
    float4 rv = r4[t];
    float4 pv = phi4[t];
    float mu[4] = {5.0f * (1.0f + xv.x), 5.0f * (1.0f + xv.y),
                   5.0f * (1.0f + xv.z), 5.0f * (1.0f + xv.w)};
    float r[4]  = {rv.x, rv.y, rv.z, rv.w};
    float p0[4] = {pv.x, pv.y, pv.z, pv.w};

    // one-step rotation constants + Chebyshev coefficient k = 2*cos(dphi)
    float cd[4], sd[4], k[4];
    #pragma unroll
    for (int j = 0; j < 4; j++) {
        sincosf(dp[j], &sd[j], &cd[j]);
        k[j] = 2.0f * cd[j];
    }

    float4* zs = out4 + t;

    float cm[4], c[4];

    #pragma unroll 1
    for (int s0 = 0; s0 < STEPS; s0 += ANCHOR) {
        // anchor: exact trig re-seed of the cosine recurrence
        #pragma unroll
        for (int j = 0; j < 4; j++) {
            float ph = fmaf((float)s0, dp[j], p0[j]);
            float c0, sn0;
            sincosf(ph, &sn0, &c0);
            cm[j] = c0;                            // cos(phi_s0)
            c[j]  = fmaf(c0, cd[j], -sn0 * sd[j]); // cos(phi_s0 + dphi)
        }

        #pragma unroll
        for (int i = 0; i < ANCHOR; i++) {
            float z[4];
            #pragma unroll
            for (int j = 0; j < 4; j++) {
                // r_{n+1} = r + (mu - r^2) * r * dt
                float tt = fmaf(-r[j], r[j], mu[j]);
                r[j] = fmaf(tt * r[j], DT, r[j]);
                // Re(z_{n+1}) = r_{n+1} * cos(phi_{n+1})
                z[j] = r[j] * c[j];
                // Chebyshev: c_{next} = k*c - c_{prev}
                float cn = fmaf(k[j], c[j], -cm[j]);
                cm[j] = c[j]; c[j] = cn;
            }
            __stcs(&zs[(size_t)(s0 + i) * BD4], make_float4(z[0], z[1], z[2], z[3]));
        }
    }

    // tails: r_f then phi_f
    out4[(size_t)STEPS * BD4 + t] = make_float4(r[0], r[1], r[2], r[3]);
    out4[(size_t)STEPS * BD4 + BD4 + t] =
        make_float4(fmaf((float)STEPS, dp[0], p0[0]), fmaf((float)STEPS, dp[1], p0[1]),
                    fmaf((float)STEPS, dp[2], p0[2]), fmaf((float)STEPS, dp[3], p0[3]));
}

extern "C" void kernel_launch(void* const* d_in, const int* in_sizes, int n_in,
                              void* d_out, int out_size)
{
    // ABI (confirmed R7): {x[131072], r[131072], phi[131072], omegas_raw[1024]},
    // out = 33,816,576 float32.
    const float* x   = (const float*)d_in[0];
    const float* r   = (const float*)d_in[1];
    const float* phi = (const float*)d_in[2];
    const float* w   = (const float*)d_in[3];

    // order-agnostic safety net
    {
        const float* big[3] = {0, 0, 0};
        const float* ww = 0;
        int nbig = 0;
        for (int i = 0; i < n_in; i++) {
            if (in_sizes[i] == DD) { if (!ww) ww = (const float*)d_in[i]; }
            else if (in_sizes[i] == BD && nbig < 3) big[nbig++] = (const float*)d_in[i];
        }
        if (ww && nbig == 3) { x = big[0]; r = big[1]; phi = big[2]; w = ww; }
    }

    muhopf_kernel<<<BD4 / 32, 32>>>((const float4*)x, (const float4*)r,
                                    (const float4*)phi, (const float4*)w,
                                    (float4*)d_out);
}